// round 3
// baseline (speedup 1.0000x reference)
#include <cuda_runtime.h>
#include <math.h>
#include <float.h>

// Problem dims
#define NV 32000
#define ND 256
#define NH 512
#define NB 16
#define NS 400
#define NT 100
#define NEX 50
#define NVX 32050   // NV + NEX
#define G4 2048     // 4*NH
#define NBLK 128    // persistent-kernel grid (<= SM count, all co-resident)

// ---------------- scratch (__device__ globals; no cudaMalloc allowed) ----------------
__device__ float dEncWT_f[768 * G4];      // rows 0..255 WihT (D), 256..767 WhhT (H)
__device__ float dEncWT_b[768 * G4];
__device__ float dDecWT[1024 * G4];       // rows 0..511 dec_WihT (2D), 512..1023 dec_WhhT
__device__ float dWprojT[1024 * NH];
__device__ float dW2hT[1024 * NH];
__device__ float dW2cT[1024 * NH];
__device__ float dWo1T[1024 * NH];
__device__ float dWo2T[NH * ND];
__device__ float dEmbT[ND * NV];          // emb transposed [k][v]

__device__ float d_gx[2 * NB * NS * G4];  // precomputed x-part of encoder gates (104.9MB)

__device__ float d_hf[2 * NB * NH];       // ping-pong h (fwd)
__device__ float d_hb[2 * NB * NH];       // ping-pong h (bwd)
__device__ float d_cf[NB * NH], d_cb[NB * NH];   // final encoder c only
__device__ float d_ys[NB * NS * 1024];    // [b][s][ys_f(512) | ys_b(512)]
__device__ float d_enc[NB * NS * NH];     // projected encoder outputs
__device__ float d_dh[2 * NB * NH];       // decoder h ping-pong (buf0 = init)
__device__ float d_dc[2 * NB * NH];       // decoder c ping-pong
__device__ float d_ctx[NB * NH];
__device__ float d_attn[NB * NS];
__device__ float d_scores[NB * NS];
__device__ float d_pgen[NB];
__device__ float d_tmp1[NB * NH];
__device__ float d_dout[NB * ND];
__device__ float d_seqmean[NB * NH];
__device__ float d_logits[NB * NV];
__device__ float d_pm[NBLK];
__device__ float d_ps[NBLK];

// ---------------- software grid barrier (all NBLK blocks co-resident) ----------------
__device__ unsigned int g_bar_arrive = 0;
__device__ volatile unsigned int g_bar_gen = 0;

__device__ __forceinline__ void grid_barrier() {
    __syncthreads();
    if (threadIdx.x == 0) {
        __threadfence();                       // release all prior writes
        unsigned int gen = g_bar_gen;
        if (atomicAdd(&g_bar_arrive, 1u) == NBLK - 1u) {
            g_bar_arrive = 0;
            __threadfence();
            g_bar_gen = gen + 1u;
        } else {
            while (g_bar_gen == gen) { __nanosleep(64); }
        }
        __threadfence();                       // acquire
    }
    __syncthreads();
}

// ---------------- helpers ----------------
__device__ __forceinline__ float sigf(float x) { return 1.0f / (1.0f + expf(-x)); }

__device__ __forceinline__ float warpReduceSum(float v) {
#pragma unroll
    for (int o = 16; o > 0; o >>= 1) v += __shfl_xor_sync(0xffffffffu, v, o);
    return v;
}
__device__ __forceinline__ float warpReduceMax(float v) {
#pragma unroll
    for (int o = 16; o > 0; o >>= 1) v = fmaxf(v, __shfl_xor_sync(0xffffffffu, v, o));
    return v;
}
__device__ float blockReduceSum(float v, float* red) {
    int lane = threadIdx.x & 31, w = threadIdx.x >> 5, nw = blockDim.x >> 5;
    v = warpReduceSum(v);
    if (lane == 0) red[w] = v;
    __syncthreads();
    float r = (threadIdx.x < nw) ? red[threadIdx.x] : 0.0f;
    if (w == 0) r = warpReduceSum(r);
    if (threadIdx.x == 0) red[0] = r;
    __syncthreads();
    float res = red[0];
    __syncthreads();
    return res;
}
__device__ float blockReduceMax(float v, float* red) {
    int lane = threadIdx.x & 31, w = threadIdx.x >> 5, nw = blockDim.x >> 5;
    v = warpReduceMax(v);
    if (lane == 0) red[w] = v;
    __syncthreads();
    float r = (threadIdx.x < nw) ? red[threadIdx.x] : -FLT_MAX;
    if (w == 0) r = warpReduceMax(r);
    if (threadIdx.x == 0) red[0] = r;
    __syncthreads();
    float res = red[0];
    __syncthreads();
    return res;
}

__device__ __forceinline__ float* wsel(int id) {
    switch (id) {
        case 0: return dEncWT_f;
        case 1: return dEncWT_b;
        case 2: return dDecWT;
        case 3: return dWprojT;
        case 4: return dW2hT;
        case 5: return dW2cT;
        case 6: return dWo1T;
        case 7: return dWo2T;
        default: return dEmbT;
    }
}
__device__ __forceinline__ float* bufsel(int id) {
    switch (id) {
        case 0: return d_hf;   // buffer 0 = final encoder h (NS even)
        case 1: return d_hb;
        case 2: return d_cf;
        case 3: return d_cb;
        case 4: return d_dh;   // buffer 0 = decoder init
        case 5: return d_dc;
        case 6: return d_ctx;
        case 7: return d_seqmean;
        default: return d_tmp1;
    }
}

// ---------------- transpose: dst[(rowOff+n)*stride + m] = src[m*N + n] ----------------
__global__ void k_transpose(const float* __restrict__ src, int M, int N,
                            int wid, int rowOff, int stride) {
    __shared__ float tile[32][33];
    float* dst = wsel(wid);
    int bx = blockIdx.x, by = blockIdx.y;
    int tx = threadIdx.x, ty = threadIdx.y;
#pragma unroll
    for (int j = 0; j < 32; j += 8) {
        int n = bx * 32 + tx;
        int m = by * 32 + ty + j;
        if (n < N && m < M) tile[ty + j][tx] = src[(size_t)m * N + n];
    }
    __syncthreads();
#pragma unroll
    for (int j = 0; j < 32; j += 8) {
        int m2 = by * 32 + tx;
        int n2 = bx * 32 + ty + j;
        if (n2 < N && m2 < M) dst[(size_t)(rowOff + n2) * stride + m2] = tile[tx][ty + j];
    }
}

// ---------------- gx = gathered emb rows @ WihT, both dirs (64x64 tile GEMM) ----------
__global__ void k_gx(const int* __restrict__ source, const float* __restrict__ emb) {
    __shared__ float As[16][64];
    __shared__ float Bs[16][64];
    int dir = blockIdx.z;
    const float* W = dir ? dEncWT_b : dEncWT_f;
    int tid = threadIdx.x;
    int row0 = blockIdx.y * 64;
    int col0 = blockIdx.x * 64;
    int ty = tid >> 4, tx = tid & 15;
    float acc[4][4];
#pragma unroll
    for (int i = 0; i < 4; i++)
#pragma unroll
        for (int j = 0; j < 4; j++) acc[i][j] = 0.0f;

    int aRow = tid >> 2;
    int aK = (tid & 3) * 4;
    int row = row0 + aRow;
    int b = row / NS, s = row - b * NS;
    int tok = source[b * NS + s];
    for (int k0 = 0; k0 < ND; k0 += 16) {
        const float4 av = *reinterpret_cast<const float4*>(&emb[(size_t)tok * ND + k0 + aK]);
        As[aK + 0][aRow] = av.x;
        As[aK + 1][aRow] = av.y;
        As[aK + 2][aRow] = av.z;
        As[aK + 3][aRow] = av.w;
#pragma unroll
        for (int i = 0; i < 4; i++) {
            int idx = tid + i * 256;
            int r = idx >> 6, c = idx & 63;
            Bs[r][c] = W[(size_t)(k0 + r) * G4 + col0 + c];
        }
        __syncthreads();
#pragma unroll
        for (int kk = 0; kk < 16; kk++) {
            float4 ar = *reinterpret_cast<const float4*>(&As[kk][ty * 4]);
            float4 br = *reinterpret_cast<const float4*>(&Bs[kk][tx * 4]);
            float a[4] = {ar.x, ar.y, ar.z, ar.w};
            float bv[4] = {br.x, br.y, br.z, br.w};
#pragma unroll
            for (int i = 0; i < 4; i++)
#pragma unroll
                for (int j = 0; j < 4; j++) acc[i][j] += a[i] * bv[j];
        }
        __syncthreads();
    }
#pragma unroll
    for (int i = 0; i < 4; i++) {
        int r = row0 + ty * 4 + i;
#pragma unroll
        for (int j = 0; j < 4; j++) {
            int c = col0 + tx * 4 + j;
            d_gx[((size_t)dir * NB * NS + r) * G4 + c] = acc[i][j];
        }
    }
}

// ---------------- persistent encoder: 400 steps, both dirs, 1 grid barrier/step -------
__global__ __launch_bounds__(256) void k_encoder(const int* __restrict__ slen,
                                                 const float* __restrict__ bf,
                                                 const float* __restrict__ bb) {
    __shared__ float hsm[16 * 516];   // 33KB, stride 516 (float4-aligned, conflict-free)
    __shared__ float gsm[512];
    const int tid = threadIdx.x, bid = blockIdx.x;
    const int dir = bid >> 6;
    const int j0 = (bid & 63) << 3;
    float* hglob = dir ? d_hb : d_hf;
    const float* Wp = dir ? dEncWT_b : dEncWT_f;
    const float* bias = dir ? bb : bf;

    // zero init both h ping-pong buffers
    {
        int i = bid * 256 + tid;
        if (i < 2 * NB * NH) { d_hf[i] = 0.0f; d_hb[i] = 0.0f; }
    }

    const int g = tid >> 6, j = (tid >> 3) & 7, bh = tid & 7;
    const int col = g * NH + j0 + j;
    const int j2 = tid >> 4, b2 = tid & 15;   // cell ownership (tid < 128)
    float creg = 0.0f;
    const int mylen = (tid < 128) ? slen[b2] : 0;

    grid_barrier();

    for (int t = 0; t < NS; t++) {
        const int pos = dir ? (NS - 1 - t) : t;
        const int pbuf = (t & 1) * NB * NH;
        // snapshot h (buffer t&1)
        for (int i = tid; i < NB * NH; i += 256) {
            int bb2 = i >> 9, k = i & 511;
            hsm[bb2 * 516 + k] = hglob[pbuf + i];
        }
        __syncthreads();

        float acc0 = 0.0f, acc1 = 0.0f;
        const float4* h0 = reinterpret_cast<const float4*>(&hsm[bh * 516]);
        const float4* h1 = reinterpret_cast<const float4*>(&hsm[(bh + 8) * 516]);
#pragma unroll 4
        for (int k4 = 0; k4 < 128; k4++) {
            float4 a = h0[k4];
            float4 bq = h1[k4];
            int kk = k4 << 2;
            float w0 = Wp[(size_t)(256 + kk) * G4 + col];
            float w1 = Wp[(size_t)(257 + kk) * G4 + col];
            float w2 = Wp[(size_t)(258 + kk) * G4 + col];
            float w3 = Wp[(size_t)(259 + kk) * G4 + col];
            acc0 += w0 * a.x + w1 * a.y + w2 * a.z + w3 * a.w;
            acc1 += w0 * bq.x + w1 * bq.y + w2 * bq.z + w3 * bq.w;
        }
        float bv = bias[col];
        acc0 += bv + d_gx[((size_t)dir * NB * NS + (size_t)bh * NS + pos) * G4 + col];
        acc1 += bv + d_gx[((size_t)dir * NB * NS + (size_t)(bh + 8) * NS + pos) * G4 + col];
        gsm[g * 128 + j * 16 + bh] = acc0;
        gsm[g * 128 + j * 16 + bh + 8] = acc1;
        __syncthreads();

        if (tid < 128) {
            float iv = gsm[0 + j2 * 16 + b2];
            float fv = gsm[128 + j2 * 16 + b2];
            float gg = gsm[256 + j2 * 16 + b2];
            float ov = gsm[384 + j2 * 16 + b2];
            float cn = sigf(fv) * creg + sigf(iv) * tanhf(gg);
            float hn = sigf(ov) * tanhf(cn);
            int m = pos < mylen;
            float hold = hsm[b2 * 516 + j0 + j2];
            creg = m ? cn : creg;
            hglob[(pbuf ^ (NB * NH)) + b2 * NH + j0 + j2] = m ? hn : hold;
            d_ys[((size_t)b2 * NS + pos) * 1024 + dir * NH + j0 + j2] = m ? hn : 0.0f;
            if (t == NS - 1) {
                float* cg = dir ? d_cb : d_cf;
                cg[b2 * NH + j0 + j2] = creg;
            }
        }
        grid_barrier();
    }
}

// ---------------- projection GEMM: d_enc = d_ys(6400x1024) @ dWprojT + bproj ----------
__global__ void k_gemm_proj(const float* __restrict__ bias) {
    __shared__ float As[16][64];
    __shared__ float Bs[16][64];
    int tid = threadIdx.x;
    int row0 = blockIdx.y * 64;
    int col0 = blockIdx.x * 64;
    int ty = tid >> 4, tx = tid & 15;
    float acc[4][4];
#pragma unroll
    for (int i = 0; i < 4; i++)
#pragma unroll
        for (int j = 0; j < 4; j++) acc[i][j] = 0.0f;

    int aRow = tid >> 2;
    int aK = (tid & 3) * 4;
    for (int k0 = 0; k0 < 1024; k0 += 16) {
        const float4 av = *reinterpret_cast<const float4*>(
            &d_ys[(size_t)(row0 + aRow) * 1024 + k0 + aK]);
        As[aK + 0][aRow] = av.x;
        As[aK + 1][aRow] = av.y;
        As[aK + 2][aRow] = av.z;
        As[aK + 3][aRow] = av.w;
#pragma unroll
        for (int i = 0; i < 4; i++) {
            int idx = tid + i * 256;
            int r = idx >> 6, c = idx & 63;
            Bs[r][c] = dWprojT[(size_t)(k0 + r) * NH + col0 + c];
        }
        __syncthreads();
#pragma unroll
        for (int kk = 0; kk < 16; kk++) {
            float4 ar = *reinterpret_cast<const float4*>(&As[kk][ty * 4]);
            float4 br = *reinterpret_cast<const float4*>(&Bs[kk][tx * 4]);
            float a[4] = {ar.x, ar.y, ar.z, ar.w};
            float bv[4] = {br.x, br.y, br.z, br.w};
#pragma unroll
            for (int i = 0; i < 4; i++)
#pragma unroll
                for (int j = 0; j < 4; j++) acc[i][j] += a[i] * bv[j];
        }
        __syncthreads();
    }
#pragma unroll
    for (int i = 0; i < 4; i++) {
        int r = row0 + ty * 4 + i;
#pragma unroll
        for (int j = 0; j < 4; j++) {
            int c = col0 + tx * 4 + j;
            d_enc[(size_t)r * NH + c] = acc[i][j] + bias[c];
        }
    }
}

// ---------------- masked mean over sequence ----------------
__global__ void k_seqmean(const int* __restrict__ slen) {
    int b = blockIdx.x;
    int len = slen[b];
    float flen = (float)len;
    for (int k = threadIdx.x; k < NH; k += blockDim.x) {
        float s = 0.0f;
        for (int ss = 0; ss < len; ss++) s += d_enc[((size_t)b * NS + ss) * NH + k];
        d_seqmean[b * NH + k] = s / flen;
    }
}

// ---------------- generic 2-input linear: out(16x512) = [in0,in1] @ WT + bias ---------
__global__ void k_lin_t2(int in0id, int in1id, int wid2, const float* __restrict__ bias,
                         int outid, int act) {
    const float* in0 = bufsel(in0id);
    const float* in1 = bufsel(in1id);
    const float* W = (wid2 == 0) ? dW2hT : (wid2 == 1) ? dW2cT : dWo1T;
    float* out = bufsel(outid);
    int idx = blockIdx.x * blockDim.x + threadIdx.x;
    int b = idx >> 9;
    int j = idx & 511;
    float a = 0.0f;
#pragma unroll 4
    for (int k = 0; k < NH; k++) {
        a += in0[b * NH + k] * W[(size_t)k * NH + j];
        a += in1[b * NH + k] * W[(size_t)(k + NH) * NH + j];
    }
    a += bias[j];
    out[idx] = act ? tanhf(a) : a;
}

// ---------------- d_dout(16x256) = d_tmp1(16x512) @ dWo2T(512x256) ----------------
__global__ void k_lin_k512() {
    int b = blockIdx.x;
    int j = threadIdx.x;
    float a = 0.0f;
#pragma unroll 4
    for (int k = 0; k < NH; k++) a += d_tmp1[b * NH + k] * dWo2T[(size_t)k * ND + j];
    d_dout[b * ND + j] = a;
}

// ---------------- persistent decoder: 100 steps, all phases fused ----------------
__global__ __launch_bounds__(256) void k_decoder(
    const int* __restrict__ target, const int* __restrict__ srcext,
    const int* __restrict__ slen, const float* __restrict__ emb,
    const float* __restrict__ decb, const float* __restrict__ bo1v,
    const float* __restrict__ Wpgen, const float* __restrict__ bpgen,
    float* __restrict__ out)
{
    __shared__ float SMB[8 * 1028];   // 32.9KB multi-purpose
    __shared__ float gsm[256];
    __shared__ float red[32];
    const int tid = threadIdx.x, bid = blockIdx.x;

    for (int t = 0; t < NT; t++) {
        const int pcur = (t & 1) * NB * NH;
        const int pnxt = ((t + 1) & 1) * NB * NH;
        float* outrow_base = out + (size_t)t * NB * NVX;

        // ---- phase 1: gates + cell (block = (bgroup of 8, j-chunk of 8)) ----
        {
            int bg = bid >> 6, j0 = (bid & 63) << 3;
            for (int idx = tid; idx < 8 * 1024; idx += 256) {
                int bb = idx >> 10, k = idx & 1023;
                int b = bg * 8 + bb;
                float v;
                if (k < ND) v = emb[(size_t)target[b * NT + t] * ND + k];
                else if (k < 2 * ND) v = d_dout[b * ND + k - ND];
                else v = d_dh[pcur + b * NH + k - 2 * ND];
                SMB[bb * 1028 + k] = v;
            }
            __syncthreads();
            int g = tid >> 6, j = (tid >> 3) & 7, bh = tid & 7;
            int col = g * NH + j0 + j;
            const float4* xr = reinterpret_cast<const float4*>(&SMB[bh * 1028]);
            float acc = 0.0f;
#pragma unroll 4
            for (int k4 = 0; k4 < 256; k4++) {
                float4 x = xr[k4];
                int kk = k4 << 2;
                acc += dDecWT[(size_t)(kk + 0) * G4 + col] * x.x;
                acc += dDecWT[(size_t)(kk + 1) * G4 + col] * x.y;
                acc += dDecWT[(size_t)(kk + 2) * G4 + col] * x.z;
                acc += dDecWT[(size_t)(kk + 3) * G4 + col] * x.w;
            }
            gsm[tid] = acc;   // layout g*64 + j*8 + bh
            __syncthreads();
            if (tid < 64) {
                int jj2 = tid >> 3, b2 = tid & 7;
                int b = bg * 8 + b2, jj = j0 + jj2;
                float iv = gsm[0   + jj2 * 8 + b2] + decb[jj];
                float fv = gsm[64  + jj2 * 8 + b2] + decb[NH + jj];
                float gg = gsm[128 + jj2 * 8 + b2] + decb[2 * NH + jj];
                float ov = gsm[192 + jj2 * 8 + b2] + decb[3 * NH + jj];
                float c = d_dc[pcur + b * NH + jj];
                float cn = sigf(fv) * c + sigf(iv) * tanhf(gg);
                float hn = sigf(ov) * tanhf(cn);
                d_dc[pnxt + b * NH + jj] = cn;
                d_dh[pnxt + b * NH + jj] = hn;
            }
        }
        grid_barrier();

        // ---- phase 2: attention scores (block = (b, s-chunk of 50)) ----
        {
            int b = bid >> 3, s0 = (bid & 7) * 50;
            for (int i = tid; i < NH; i += 256) SMB[i] = d_dh[pnxt + b * NH + i];
            __syncthreads();
            int lane = tid & 31, warp = tid >> 5;
            int len = slen[b];
            for (int s = s0 + warp; s < s0 + 50; s += 8) {
                const float* er = &d_enc[((size_t)b * NS + s) * NH];
                float p = 0.0f;
#pragma unroll 4
                for (int k = lane; k < NH; k += 32) p += SMB[k] * er[k];
                p = warpReduceSum(p);
                if (lane == 0) d_scores[b * NS + s] = (s < len) ? p : -3.402823466e38f;
            }
        }
        grid_barrier();

        // ---- phase 3: softmax + context + p_gen (blocks 0..15) ----
        if (bid < NB) {
            int b = bid;
            for (int s = tid; s < NS; s += 256) SMB[s] = d_scores[b * NS + s];
            for (int k = tid; k < NH; k += 256) SMB[1024 + k] = d_dh[pnxt + b * NH + k];
            __syncthreads();
            float m = -FLT_MAX;
            for (int s = tid; s < NS; s += 256) m = fmaxf(m, SMB[s]);
            float M = blockReduceMax(m, red);
            float su = 0.0f;
            for (int s = tid; s < NS; s += 256) {
                float e = expf(SMB[s] - M);
                SMB[s] = e;
                su += e;
            }
            float S = blockReduceSum(su, red);
            float inv = 1.0f / S;
            for (int s = tid; s < NS; s += 256) {
                float a = SMB[s] * inv;
                SMB[s] = a;
                d_attn[b * NS + s] = a;
            }
            __syncthreads();
            float a0 = 0.0f, a1 = 0.0f;
            for (int s = 0; s < NS; s++) {
                float a = SMB[s];
                const float* er = &d_enc[((size_t)b * NS + s) * NH];
                a0 += a * er[tid];
                a1 += a * er[tid + 256];
            }
            SMB[512 + tid] = a0;
            SMB[512 + 256 + tid] = a1;
            d_ctx[b * NH + tid] = a0;
            d_ctx[b * NH + tid + 256] = a1;
            __syncthreads();
            int tok = target[b * NT + t];
            float p = 0.0f;
            for (int k = tid; k < 1536; k += 256) {
                float cv;
                if (k < NH) cv = SMB[512 + k];
                else if (k < 2 * NH) cv = SMB[1024 + (k - NH)];
                else {
                    int kk = k - 2 * NH;
                    cv = (kk < ND) ? emb[(size_t)tok * ND + kk] : d_dout[b * ND + kk - ND];
                }
                p += Wpgen[k] * cv;
            }
            float pt = blockReduceSum(p, red);
            if (tid == 0) d_pgen[b] = 1.0f / (1.0f + expf(-(pt + bpgen[0])));
        }
        grid_barrier();

        // ---- phase 4: tmp1 = tanh([h,ctx] @ Wo1T + bo1)  (64 outs/block, 4-way K) ----
        {
            int oi = bid * 64 + (tid & 63);
            int q = tid >> 6;
            int b = oi >> 9, jj = oi & 511;
            int ks = q * 256;
            float acc = 0.0f;
#pragma unroll 4
            for (int k = ks; k < ks + 256; k++) {
                float iv = (k < NH) ? d_dh[pnxt + b * NH + k] : d_ctx[b * NH + k - NH];
                acc += iv * dWo1T[(size_t)k * NH + jj];
            }
            gsm[tid] = acc;
            __syncthreads();
            if (tid < 64) {
                float s = gsm[tid] + gsm[64 + tid] + gsm[128 + tid] + gsm[192 + tid];
                d_tmp1[oi] = tanhf(s + bo1v[jj]);
            }
        }
        grid_barrier();

        // ---- phase 5: dec_out = tmp1 @ Wo2T  (32 outs/block, 8-way K) ----
        {
            int oi = bid * 32 + (tid & 31);
            int q = tid >> 5;
            int b = oi >> 8, jj = oi & 255;
            int ks = q * 64;
            float acc = 0.0f;
#pragma unroll 4
            for (int k = ks; k < ks + 64; k++)
                acc += d_tmp1[b * NH + k] * dWo2T[(size_t)k * ND + jj];
            gsm[tid] = acc;
            __syncthreads();
            if (tid < 32) {
                float s = 0.0f;
#pragma unroll
                for (int q2 = 0; q2 < 8; q2++) s += gsm[q2 * 32 + tid];
                d_dout[bid * 32 + tid] = s;
            }
        }
        grid_barrier();

        // ---- phase 6: logits = dec_out @ embT  (250 vocab cols/block) ----
        {
            for (int i = tid; i < NB * ND; i += 256) SMB[i] = d_dout[i];
            __syncthreads();
            if (tid < 250) {
                int v = bid * 250 + tid;
                float acc[NB];
#pragma unroll
                for (int b = 0; b < NB; b++) acc[b] = 0.0f;
                for (int k = 0; k < ND; k += 4) {
                    float e0 = dEmbT[(size_t)(k + 0) * NV + v];
                    float e1 = dEmbT[(size_t)(k + 1) * NV + v];
                    float e2 = dEmbT[(size_t)(k + 2) * NV + v];
                    float e3 = dEmbT[(size_t)(k + 3) * NV + v];
#pragma unroll
                    for (int b = 0; b < NB; b++) {
                        const float4 dd = *reinterpret_cast<const float4*>(&SMB[b * ND + k]);
                        acc[b] += e0 * dd.x + e1 * dd.y + e2 * dd.z + e3 * dd.w;
                    }
                }
#pragma unroll
                for (int b = 0; b < NB; b++) d_logits[(size_t)b * NV + v] = acc[b];
            }
        }
        grid_barrier();

        // ---- phase 7: per-chunk online softmax partials (16b x 8 chunks) ----
        {
            int b = bid >> 3, base = (bid & 7) * 4000;
            float mt = -FLT_MAX, st = 0.0f;
            for (int v = base + tid; v < base + 4000; v += 256) {
                float x = d_logits[(size_t)b * NV + v];
                if (x > mt) { st = st * expf(mt - x) + 1.0f; mt = x; }
                else st += expf(x - mt);
            }
            float M = blockReduceMax(mt, red);
            float sadj = (mt == -FLT_MAX) ? 0.0f : st * expf(mt - M);
            float S = blockReduceSum(sadj, red);
            if (tid == 0) { d_pm[bid] = M; d_ps[bid] = S; }
        }
        grid_barrier();

        // ---- phase 8: combine + write scaled vocab dist (covers NVX incl. extra) ----
        {
            int b = bid >> 3, ch = bid & 7;
            float M = -FLT_MAX;
#pragma unroll
            for (int i = 0; i < 8; i++) M = fmaxf(M, d_pm[b * 8 + i]);
            float S = 0.0f;
#pragma unroll
            for (int i = 0; i < 8; i++) S += d_ps[b * 8 + i] * expf(d_pm[b * 8 + i] - M);
            float scale = d_pgen[b] / S;
            float* row = outrow_base + (size_t)b * NVX;
            int base = ch * 4007;
            int end = base + 4007; if (end > NVX) end = NVX;
            for (int v = base + tid; v < end; v += 256)
                row[v] = (v < NV) ? scale * expf(d_logits[(size_t)b * NV + v] - M) : 0.0f;
        }
        grid_barrier();

        // ---- phase 9: scatter-add (1-p_gen)*attn ----
        if (bid < 25) {
            int idx = bid * 256 + tid;  // exactly 6400
            int b = idx / NS, s = idx - b * NS;
            float val = (1.0f - d_pgen[b]) * d_attn[b * NS + s];
            atomicAdd(outrow_base + (size_t)b * NVX + srcext[b * NS + s], val);
        }
        grid_barrier();

        // ---- phase 10: log(x + 1e-20) ----
        for (int i = bid * 256 + tid; i < NB * NVX; i += NBLK * 256) {
            float* p = outrow_base + i;
            *p = logf(*p + 1e-20f);
        }
        grid_barrier();
    }
}

// ================================ host side ================================
extern "C" void kernel_launch(void* const* d_in, const int* in_sizes, int n_in,
                              void* d_out, int out_size) {
    const int* source   = (const int*)d_in[0];
    const int* srcext   = (const int*)d_in[1];
    const int* slen     = (const int*)d_in[2];
    const int* target   = (const int*)d_in[3];
    const float* emb    = (const float*)d_in[4];
    const float* eWih_f = (const float*)d_in[5];
    const float* eWhh_f = (const float*)d_in[6];
    const float* eb_f   = (const float*)d_in[7];
    const float* eWih_b = (const float*)d_in[8];
    const float* eWhh_b = (const float*)d_in[9];
    const float* eb_b   = (const float*)d_in[10];
    const float* Wproj  = (const float*)d_in[11];
    const float* bproj  = (const float*)d_in[12];
    const float* W2h    = (const float*)d_in[13];
    const float* b2h    = (const float*)d_in[14];
    const float* W2c    = (const float*)d_in[15];
    const float* b2c    = (const float*)d_in[16];
    const float* Wo1    = (const float*)d_in[17];
    const float* bo1    = (const float*)d_in[18];
    const float* Wo2    = (const float*)d_in[19];
    const float* dWih   = (const float*)d_in[20];
    const float* dWhh   = (const float*)d_in[21];
    const float* db     = (const float*)d_in[22];
    const float* Wpgen  = (const float*)d_in[23];
    const float* bpgen  = (const float*)d_in[24];
    float* out = (float*)d_out;

    dim3 tb(32, 8);
    k_transpose<<<dim3(8, 64), tb>>>(eWih_f, 2048, 256, 0, 0, G4);
    k_transpose<<<dim3(16, 64), tb>>>(eWhh_f, 2048, 512, 0, 256, G4);
    k_transpose<<<dim3(8, 64), tb>>>(eWih_b, 2048, 256, 1, 0, G4);
    k_transpose<<<dim3(16, 64), tb>>>(eWhh_b, 2048, 512, 1, 256, G4);
    k_transpose<<<dim3(16, 64), tb>>>(dWih, 2048, 512, 2, 0, G4);
    k_transpose<<<dim3(16, 64), tb>>>(dWhh, 2048, 512, 2, 512, G4);
    k_transpose<<<dim3(32, 16), tb>>>(Wproj, 512, 1024, 3, 0, NH);
    k_transpose<<<dim3(32, 16), tb>>>(W2h, 512, 1024, 4, 0, NH);
    k_transpose<<<dim3(32, 16), tb>>>(W2c, 512, 1024, 5, 0, NH);
    k_transpose<<<dim3(32, 16), tb>>>(Wo1, 512, 1024, 6, 0, NH);
    k_transpose<<<dim3(16, 8), tb>>>(Wo2, 256, 512, 7, 0, ND);
    k_transpose<<<dim3(8, 1000), tb>>>(emb, NV, ND, 8, 0, NV);

    // x-part of encoder gates for all positions, both dirs (one batched GEMM)
    k_gx<<<dim3(32, 100, 2), 256>>>(source, emb);

    // persistent encoder (single graph node for 400 steps)
    k_encoder<<<NBLK, 256>>>(slen, eb_f, eb_b);

    // projection + decoder init
    k_gemm_proj<<<dim3(8, 100), 256>>>(bproj);
    k_seqmean<<<NB, 256>>>(slen);
    k_lin_t2<<<32, 256>>>(0, 1, 0, b2h, 4, 0);   // dec_h
    k_lin_t2<<<32, 256>>>(2, 3, 1, b2c, 5, 0);   // dec_c
    k_lin_t2<<<32, 256>>>(4, 7, 2, bo1, 8, 1);   // tmp1
    k_lin_k512<<<NB, 256>>>();                   // dec_out0

    // persistent decoder (single graph node for 100 steps)
    k_decoder<<<NBLK, 256>>>(target, srcext, slen, emb, db, bo1, Wpgen, bpgen, out);
}